// round 17
// baseline (speedup 1.0000x reference)
#include <cuda_runtime.h>
#include <cstdint>

// CARAFE: features [2,64,64,128] f32 NHWC, masks [2,128,128,25] f32.
// Output [2,128,128,128] f32. k=5, G=1, Cg=128. 2x nearest: src = dst/2.
//
// Warp = 4 adjacent centers (bx0..bx0+3) -> 16 outputs. 5x8 union window:
// 40 feature LDG.128 serve 100 tap-uses (10/center, was 15), batched
// 8/row (MLP=8). 2048 warps, 512 blocks, 128-reg cap -> 4 blocks/SM ->
// single wave. Weights normalized in prologue (e/sum, OOB taps -> 0,
// matching reference zero-padding) and stored paired for fp32x2 FMA.

#define FEAT_H 64
#define FEAT_W 64
#define OUT_H 128
#define OUT_W 128
#define C4 32
#define K 5
#define K2 25
#define WARPS 4
#define CPW 4            // centers per warp

__global__ __launch_bounds__(32 * WARPS, 4)
void carafe_kernel(const float* __restrict__ feat,
                   const float* __restrict__ masks,
                   float* __restrict__ out)
{
    const int tid  = threadIdx.x;
    const int wid  = tid >> 5;
    const int lane = tid & 31;

    // warp-group id -> (b, by, gx); 16 x-groups of 4 centers per row
    const int g  = blockIdx.x * WARPS + wid;
    const int gx = g & 15;
    const int by = (g >> 4) & 63;
    const int b  = g >> 10;
    const int bx0 = 4 * gx;

    // normalized weights, paired: [warp][center][tap][output] = (w, w)
    __shared__ __align__(16) float2 wsh[WARPS][CPW][K2][4];

    // ---- prologue: 16 softmaxes (4 centers x 4 outputs) ----
    const int tdi = lane / K, tdj = lane % K;
    const bool vy = ((unsigned)(by + tdi - 2) < (unsigned)FEAT_H);

    #pragma unroll
    for (int c = 0; c < CPW; c++) {
        const int bx = bx0 + c;
        const bool valid = vy & ((unsigned)(bx + tdj - 2) < (unsigned)FEAT_W);
        const float* mbase =
            masks + (((size_t)b * OUT_H + 2 * by) * OUT_W + 2 * bx) * K2;
        #pragma unroll
        for (int o = 0; o < 4; o++) {
            const float* mp = mbase + ((o >> 1) * (size_t)OUT_W + (o & 1)) * K2;
            // logits are N(0,1)-scale: exp cannot overflow
            float e = (lane < K2) ? __expf(__ldg(mp + lane)) : 0.f;
            float s = e;
            #pragma unroll
            for (int off = 16; off; off >>= 1)
                s += __shfl_xor_sync(0xffffffffu, s, off);
            if (lane < K2) {
                const float wv = valid ? __fdividef(e, s) : 0.f;  // OOB -> 0
                wsh[wid][c][lane][o] = make_float2(wv, wv);
            }
        }
    }
    __syncwarp();

    const uint32_t wb0 = (uint32_t)__cvta_generic_to_shared(&wsh[wid][0][0][0]);

    // ---- mainloop: 5 rows x 8 union columns ----
    const float4* fb = (const float4*)feat
                     + (size_t)b * FEAT_H * FEAT_W * C4 + lane;

    uint64_t acc[CPW][4][2];
    #pragma unroll
    for (int c = 0; c < CPW; c++)
        #pragma unroll
        for (int o = 0; o < 4; o++)
            acc[c][o][0] = acc[c][o][1] = 0;

    #pragma unroll
    for (int di = 0; di < K; di++) {
        const int y = min(max(by + di - 2, 0), FEAT_H - 1);
        const float4* frow = fb + (size_t)y * FEAT_W * C4;

        // batch-load the 8 union columns (independent -> MLP = 8)
        uint64_t f0[8], f1[8];
        #pragma unroll
        for (int u = 0; u < 8; u++) {
            const int x = min(max(bx0 + u - 2, 0), FEAT_W - 1);
            asm("ld.global.nc.v2.u64 {%0,%1}, [%2];"
                : "=l"(f0[u]), "=l"(f1[u]) : "l"(frow + (size_t)x * C4));
        }

        // apply: center c uses union cols u = c..c+4 (tap dj = u - c)
        #pragma unroll
        for (int u = 0; u < 8; u++) {
            #pragma unroll
            for (int c = 0; c < CPW; c++) {
                if (c <= u && u - c <= 4) {
                    const int t = di * K + (u - c);
                    const uint32_t wa = wb0 + (c * K2 + t) * 32;
                    uint64_t w0, w1, w2, w3;
                    asm("ld.shared.v2.u64 {%0,%1}, [%2];"
                        : "=l"(w0), "=l"(w1) : "r"(wa));
                    asm("ld.shared.v2.u64 {%0,%1}, [%2];"
                        : "=l"(w2), "=l"(w3) : "r"(wa + 16));
                    asm("fma.rn.f32x2 %0, %1, %2, %0;"
                        : "+l"(acc[c][0][0]) : "l"(w0), "l"(f0[u]));
                    asm("fma.rn.f32x2 %0, %1, %2, %0;"
                        : "+l"(acc[c][0][1]) : "l"(w0), "l"(f1[u]));
                    asm("fma.rn.f32x2 %0, %1, %2, %0;"
                        : "+l"(acc[c][1][0]) : "l"(w1), "l"(f0[u]));
                    asm("fma.rn.f32x2 %0, %1, %2, %0;"
                        : "+l"(acc[c][1][1]) : "l"(w1), "l"(f1[u]));
                    asm("fma.rn.f32x2 %0, %1, %2, %0;"
                        : "+l"(acc[c][2][0]) : "l"(w2), "l"(f0[u]));
                    asm("fma.rn.f32x2 %0, %1, %2, %0;"
                        : "+l"(acc[c][2][1]) : "l"(w2), "l"(f1[u]));
                    asm("fma.rn.f32x2 %0, %1, %2, %0;"
                        : "+l"(acc[c][3][0]) : "l"(w3), "l"(f0[u]));
                    asm("fma.rn.f32x2 %0, %1, %2, %0;"
                        : "+l"(acc[c][3][1]) : "l"(w3), "l"(f1[u]));
                }
            }
        }
    }

    // ---- write the four 2x2 output quads ----
    float4* __restrict__ o4 = (float4*)out;
    const size_t rs = (size_t)OUT_W * C4;
    #pragma unroll
    for (int c = 0; c < CPW; c++) {
        float4* ob = o4 + (((size_t)b * OUT_H + 2 * by) * OUT_W
                           + 2 * (bx0 + c)) * C4 + lane;
        asm volatile("st.global.v2.u64 [%0], {%1,%2};"
                     :: "l"(ob),           "l"(acc[c][0][0]), "l"(acc[c][0][1]) : "memory");
        asm volatile("st.global.v2.u64 [%0], {%1,%2};"
                     :: "l"(ob + C4),      "l"(acc[c][1][0]), "l"(acc[c][1][1]) : "memory");
        asm volatile("st.global.v2.u64 [%0], {%1,%2};"
                     :: "l"(ob + rs),      "l"(acc[c][2][0]), "l"(acc[c][2][1]) : "memory");
        asm volatile("st.global.v2.u64 [%0], {%1,%2};"
                     :: "l"(ob + rs + C4), "l"(acc[c][3][0]), "l"(acc[c][3][1]) : "memory");
    }
}

extern "C" void kernel_launch(void* const* d_in, const int* in_sizes, int n_in,
                              void* d_out, int out_size)
{
    const float* feat  = (const float*)d_in[0];   // [2,64,64,128]
    const float* masks = (const float*)d_in[1];   // [2,128,128,25]
    float* out = (float*)d_out;                   // [2,128,128,128]

    const int n_groups = 2 * FEAT_H * (FEAT_W / CPW);   // 2048
    carafe_kernel<<<n_groups / WARPS, 32 * WARPS>>>(feat, masks, out);
}